// round 13
// baseline (speedup 1.0000x reference)
#include <cuda_runtime.h>

// PixCorr: per-row Pearson correlation over [256, 196608] fp32 rows, then
// mean over rows. Single kernel, "fused-lite" epilogue:
//  - Mainloop identical to the proven fastest streamer (one CTA per row,
//    256 x 1024, plain cached float4 loads, unroll 4).
//  - Epilogue confined to warp 0: lane0 stores g_corr[row], __threadfence,
//    atomic ticket; ticket broadcast by shfl (NO trailing __syncthreads --
//    warps 1..31 retire immediately). Last CTA's warp 0 alone reduces the
//    256 corrs (8 per lane + shfl) and writes d_out[0]; resets the ticket
//    for graph-replay determinism. Fully deterministic combine order.

#define NROWS   256
#define D_ELEMS 196608          // 3*256*256
#define NVEC    (D_ELEMS / 4)   // 49152 float4 per row
#define THREADS 1024
#define EPS     1e-6f

__device__ float        g_corr[NROWS];
__device__ unsigned int g_ticket;   // zero-initialized at module load

__device__ __forceinline__ float warp_sum(float v) {
    v += __shfl_xor_sync(0xFFFFFFFFu, v, 16);
    v += __shfl_xor_sync(0xFFFFFFFFu, v, 8);
    v += __shfl_xor_sync(0xFFFFFFFFu, v, 4);
    v += __shfl_xor_sync(0xFFFFFFFFu, v, 2);
    v += __shfl_xor_sync(0xFFFFFFFFu, v, 1);
    return v;
}

__global__ __launch_bounds__(THREADS, 1)
void pixcorr_fusedlite_kernel(const float* __restrict__ preds,
                              const float* __restrict__ targets,
                              float* __restrict__ out) {
    const int row = blockIdx.x;
    const float4* __restrict__ z4 =
        reinterpret_cast<const float4*>(targets + (size_t)row * D_ELEMS);
    const float4* __restrict__ b4 =
        reinterpret_cast<const float4*>(preds + (size_t)row * D_ELEMS);

    float sz = 0.f, sb = 0.f, szz = 0.f, sbb = 0.f, szb = 0.f;

    // 48 iterations per thread, fully coalesced plain cached float4 loads.
    #pragma unroll 4
    for (int i = threadIdx.x; i < NVEC; i += THREADS) {
        float4 zv = z4[i];
        float4 bv = b4[i];
        sz  += (zv.x + zv.y) + (zv.z + zv.w);
        sb  += (bv.x + bv.y) + (bv.z + bv.w);
        szz  = fmaf(zv.x, zv.x, fmaf(zv.y, zv.y, fmaf(zv.z, zv.z, fmaf(zv.w, zv.w, szz))));
        sbb  = fmaf(bv.x, bv.x, fmaf(bv.y, bv.y, fmaf(bv.z, bv.z, fmaf(bv.w, bv.w, sbb))));
        szb  = fmaf(zv.x, bv.x, fmaf(zv.y, bv.y, fmaf(zv.z, bv.z, fmaf(zv.w, bv.w, szb))));
    }

    sz  = warp_sum(sz);
    sb  = warp_sum(sb);
    szz = warp_sum(szz);
    sbb = warp_sum(sbb);
    szb = warp_sum(szb);

    __shared__ float sh[5][THREADS / 32];
    const int lane = threadIdx.x & 31;
    const int wid  = threadIdx.x >> 5;
    if (lane == 0) {
        sh[0][wid] = sz;  sh[1][wid] = sb;
        sh[2][wid] = szz; sh[3][wid] = sbb; sh[4][wid] = szb;
    }
    __syncthreads();

    // Everything below runs in warp 0 only; warps 1..31 exit here.
    if (threadIdx.x < 32) {
        float a0 = warp_sum(sh[0][lane]);
        float a1 = warp_sum(sh[1][lane]);
        float a2 = warp_sum(sh[2][lane]);
        float a3 = warp_sum(sh[3][lane]);
        float a4 = warp_sum(sh[4][lane]);

        unsigned int t = 0u;
        if (lane == 0) {
            const float invD = 1.0f / (float)D_ELEMS;
            float cov = a4 - a0 * a1 * invD;
            float vz  = fmaxf(a2 - a0 * a0 * invD, 0.f);
            float vb  = fmaxf(a3 - a1 * a1 * invD, 0.f);
            g_corr[row] = cov / (sqrtf(vz) * sqrtf(vb) + EPS);

            __threadfence();                      // release g_corr[row]
            t = atomicAdd(&g_ticket, 1u);
        }
        t = __shfl_sync(0xFFFFFFFFu, t, 0);

        if (t == NROWS - 1u) {
            __threadfence();                      // acquire all g_corr
            float s = 0.f;
            #pragma unroll
            for (int i = 0; i < NROWS / 32; i++)
                s += g_corr[lane + i * 32];
            s = warp_sum(s);
            if (lane == 0) {
                out[0] = s * (1.0f / (float)NROWS);
                g_ticket = 0;                     // reset for next replay
                __threadfence();
            }
        }
    }
}

extern "C" void kernel_launch(void* const* d_in, const int* in_sizes, int n_in,
                              void* d_out, int out_size) {
    const float* preds   = (const float*)d_in[0];
    const float* targets = (const float*)d_in[1];
    float* out = (float*)d_out;

    pixcorr_fusedlite_kernel<<<NROWS, THREADS>>>(preds, targets, out);
}